// round 15
// baseline (speedup 1.0000x reference)
#include <cuda_runtime.h>
#include <cuda_bf16.h>

#define GRIDN   32
#define NPLANE  1089        // 33*33
#define NVOL    35937       // 33^3
#define T_ROWS  48
#define NSUB    144         // 48 rows * 3 sub-triangles
#define NT      96
#define PPB     96          // points per block (one thread per point)

// ---------------------------------------------------------------------------
__global__ void zero_out_kernel(float4* __restrict__ out, int n4) {
    int i = blockIdx.x * blockDim.x + threadIdx.x;
    if (i < n4) out[i] = make_float4(0.f, 0.f, 0.f, 0.f);
}

__device__ __forceinline__ float safeden(float x) {
    return (fabsf(x) > 1e-12f) ? x : 1e-12f;
}

// Packed symmetric pair index for i<=j in [0,12): 0..77
__device__ __forceinline__ int pidx(int i, int j) {
    if (i > j) { int t = i; i = j; j = t; }
    return i * 12 - ((i * (i + 1)) >> 1) + j;
}

// Vector reduction: one 16-byte scattered atomic instead of four 4-byte ones.
__device__ __forceinline__ void red_add_v4(float* addr, float a, float b,
                                           float c, float d) {
    asm volatile("red.global.add.v4.f32 [%0], {%1, %2, %3, %4};"
                 :: "l"(addr), "f"(a), "f"(b), "f"(c), "f"(d) : "memory");
}

// ---------------------------------------------------------------------------
// Full-path point-triangle squared distance from 6 Gram entries.
// Classification values non-contracted (exact degenerate resolution);
// algebraic single-division distance + garbage guard.
// Selection order: interior -> BC -> AC -> C -> AB -> B -> A  (A wins).
// ---------------------------------------------------------------------------
__device__ __forceinline__ float tri_dist_g(float g_aa, float g_ab, float g_ac,
                                            float g_bb, float g_bc, float g_cc) {
    float d1 = __fsub_rn(g_aa, g_ab);
    float d2 = __fsub_rn(g_aa, g_ac);
    float d3 = __fsub_rn(g_ab, g_bb);
    float d4 = __fsub_rn(g_ab, g_bc);
    float d5 = __fsub_rn(g_ac, g_bc);
    float d6 = __fsub_rn(g_ac, g_cc);

    float va = __fsub_rn(__fmul_rn(d3, d6), __fmul_rn(d5, d4));
    float vb = __fsub_rn(__fmul_rn(d5, d2), __fmul_rn(d1, d6));
    float vc = __fsub_rn(__fmul_rn(d1, d4), __fmul_rn(d3, d2));
    float e43 = __fsub_rn(d4, d3);
    float e56 = __fsub_rn(d5, d6);

    float base = g_aa;                       // interior (default)
    float num  = vb * d1 + vc * d2;
    float den  = va + vb + vc;
    if ((va <= 0.f) && (e43 >= 0.f) && (e56 >= 0.f)) { base = g_bb; num = e43 * e43; den = e43 + e56; } // BC
    if ((vb <= 0.f) && (d2 >= 0.f) && (d6 <= 0.f))   { base = g_aa; num = d2 * d2;   den = d2 - d6;   } // AC
    if ((d6 >= 0.f) && (d5 <= d6))                   { base = g_cc; num = 0.f; }                        // C
    if ((vc <= 0.f) && (d1 >= 0.f) && (d3 <= 0.f))   { base = g_aa; num = d1 * d1;   den = d1 - d3;   } // AB
    if ((d3 >= 0.f) && (d4 <= d3))                   { base = g_bb; num = 0.f; }                        // B
    if ((d1 <= 0.f) && (d2 <= 0.f))                  { base = g_aa; num = 0.f; }                        // A

    float r = __fdividef(num, safeden(den));
    float d = fmaxf(base - r, 0.f);
    if (!((r >= 0.f) && (base - r >= -1e-4f))) d = base;   // garbage guard
    return d;
}

// ---------------------------------------------------------------------------
// Main kernel: one thread per point; per-point 78-entry Gram matrix in smem.
// Degenerate sub-triangles (duplicated vertex index) take a warp-uniform fast
// path (reference stack provably reduces to point-segment(a,b)).
// ---------------------------------------------------------------------------
__global__ void __launch_bounds__(NT)
pt_dist_kernel(const float* __restrict__ offset,
               const float* __restrict__ points,
               const int*   __restrict__ tri_table,
               float*       __restrict__ out,
               int n_pts)
{
    __shared__ float          su[78 * PPB];    // Gram entries, [entry][point]
    __shared__ unsigned short off_s[NSUB * 8]; // 6 offsets (x PPB), cls, pad

    int tid = threadIdx.x;
    for (int k = tid; k < NSUB; k += NT) {
        int a = tri_table[k * 3 + 0];
        int b = tri_table[k * 3 + 1];
        int c = tri_table[k * 3 + 2];
        off_s[k * 8 + 0] = (unsigned short)(pidx(a, a) * PPB);
        off_s[k * 8 + 1] = (unsigned short)(pidx(a, b) * PPB);
        off_s[k * 8 + 2] = (unsigned short)(pidx(a, c) * PPB);
        off_s[k * 8 + 3] = (unsigned short)(pidx(b, b) * PPB);
        off_s[k * 8 + 4] = (unsigned short)(pidx(b, c) * PPB);
        off_s[k * 8 + 5] = (unsigned short)(pidx(c, c) * PPB);
        off_s[k * 8 + 6] = ((a == b) || (a == c) || (b == c)) ? 1 : 0;
        off_s[k * 8 + 7] = 0;
    }

    int i = blockIdx.x * NT + tid;
    bool valid = (i < n_pts);
    int il = valid ? i : (n_pts - 1);

    float px = points[3 * il + 0];
    float py = points[3 * il + 1];
    float pz = points[3 * il + 2];

    int cx = min(max((int)floorf(px), 0), GRIDN - 1);
    int cy = min(max((int)floorf(py), 0), GRIDN - 1);
    int cz = min(max((int)floorf(pz), 0), GRIDN - 1);
    float lx = px - (float)cx;
    float ly = py - (float)cy;
    float lz = pz - (float)cz;

    int cb = cx * NPLANE + cy * 33 + cz;
    const float* o0 = offset;
    const float* o1 = offset + NVOL;
    const float* o2 = offset + 2 * NVOL;

    float t0  = o0[cb];
    float t1  = o1[cb + NPLANE];
    float t2  = o0[cb + 33];
    float t3  = o1[cb];
    float t4  = o0[cb + 1];
    float t5  = o1[cb + NPLANE + 1];
    float t6  = o0[cb + 33 + 1];
    float t7  = o1[cb + 1];
    float t8  = o2[cb];
    float t9  = o2[cb + NPLANE];
    float t10 = o2[cb + NPLANE + 33];
    float t11 = o2[cb + 33];

    // u_e = local - v_e for the 12 edge vertices
    float ux[12], uy[12], uz[12];
    ux[0]  = lx - t0;  uy[0]  = ly;       uz[0]  = lz;
    ux[1]  = lx - 1.f; uy[1]  = ly - t1;  uz[1]  = lz;
    ux[2]  = lx - t2;  uy[2]  = ly - 1.f; uz[2]  = lz;
    ux[3]  = lx;       uy[3]  = ly - t3;  uz[3]  = lz;
    ux[4]  = lx - t4;  uy[4]  = ly;       uz[4]  = lz - 1.f;
    ux[5]  = lx - 1.f; uy[5]  = ly - t5;  uz[5]  = lz - 1.f;
    ux[6]  = lx - t6;  uy[6]  = ly - 1.f; uz[6]  = lz - 1.f;
    ux[7]  = lx;       uy[7]  = ly - t7;  uz[7]  = lz - 1.f;
    ux[8]  = lx;       uy[8]  = ly;       uz[8]  = lz - t8;
    ux[9]  = lx - 1.f; uy[9]  = ly;       uz[9]  = lz - t9;
    ux[10] = lx - 1.f; uy[10] = ly - 1.f; uz[10] = lz - t10;
    ux[11] = lx;       uy[11] = ly - 1.f; uz[11] = lz - t11;

    // 78-entry Gram matrix (contraction OK: equal pairs share one stored value)
    #pragma unroll
    for (int a = 0; a < 12; a++) {
        #pragma unroll
        for (int b = a; b < 12; b++) {
            int p = a * 12 - ((a * (a + 1)) >> 1) + b;   // compile-time after unroll
            su[p * PPB + tid] = ux[a] * ux[b] + uy[a] * uy[b] + uz[a] * uz[b];
        }
    }
    __syncthreads();

    float* outc = out + (size_t)(((cx * GRIDN) + cy) * GRIDN + cz) * T_ROWS;

    #pragma unroll 1
    for (int t = 0; t < T_ROWS; t += 4) {
        float mq[4];
        #pragma unroll
        for (int q = 0; q < 4; q++) {
            float m = 3.402823e38f;
            #pragma unroll
            for (int s = 0; s < 3; s++) {
                int k = (t + q) * 3 + s;
                ushort4 oA = *(const ushort4*)&off_s[k * 8];      // (aa, ab, ac, bb)
                ushort4 oB = *(const ushort4*)&off_s[k * 8 + 4];  // (bc, cc, cls, pad)
                float dd;
                if (oB.z == 0) {                          // warp-uniform branch
                    float g_aa = su[oA.x + tid];
                    float g_ab = su[oA.y + tid];
                    float g_ac = su[oA.z + tid];
                    float g_bb = su[oA.w + tid];
                    float g_bc = su[oB.x + tid];
                    float g_cc = su[oB.y + tid];
                    dd = tri_dist_g(g_aa, g_ab, g_ac, g_bb, g_bc, g_cc);
                } else {
                    // degenerate: point-segment(a,b) per reference stack
                    float g_aa = su[oA.x + tid];
                    float g_ab = su[oA.y + tid];
                    float g_bb = su[oA.w + tid];
                    float d1 = __fsub_rn(g_aa, g_ab);
                    float d3 = __fsub_rn(g_ab, g_bb);
                    float r  = __fdividef(d1 * d1, safeden(d1 - d3));
                    dd = fmaxf(g_aa - r, 0.f);
                    if (d3 >= 0.f) dd = g_bb;             // B region
                    if (d1 <= 0.f) dd = g_aa;             // A region (wins)
                }
                m = fminf(m, dd);
            }
            mq[q] = m;
        }
        if (valid) red_add_v4(outc + t, mq[0], mq[1], mq[2], mq[3]);
    }
}

// ---------------------------------------------------------------------------
extern "C" void kernel_launch(void* const* d_in, const int* in_sizes, int n_in,
                              void* d_out, int out_size) {
    const float* offset    = (const float*)d_in[0];   // (3,33,33,33) fp32
    const float* points    = (const float*)d_in[1];   // (131072,3)   fp32
    const int*   tri_table = (const int*)  d_in[2];   // (48,3,3)     int32
    float* out = (float*)d_out;                       // (32768,48)   fp32

    int n_pts = in_sizes[1] / 3;

    int n4 = out_size / 4;
    zero_out_kernel<<<(n4 + 255) / 256, 256>>>((float4*)out, n4);

    int blocks = (n_pts + PPB - 1) / PPB;
    pt_dist_kernel<<<blocks, NT>>>(offset, points, tri_table, out, n_pts);
}

// round 16
// speedup vs baseline: 1.7608x; 1.7608x over previous
#include <cuda_runtime.h>
#include <cuda_bf16.h>

#define GRIDN   32
#define NPLANE  1089        // 33*33
#define NVOL    35937       // 33^3
#define T_ROWS  48
#define NSUB    144         // 48 rows * 3 sub-triangles
#define NT      128
#define PPB     128         // points per block (one thread per point)

// ---------------------------------------------------------------------------
__global__ void zero_out_kernel(float4* __restrict__ out, int n4) {
    int i = blockIdx.x * blockDim.x + threadIdx.x;
    if (i < n4) out[i] = make_float4(0.f, 0.f, 0.f, 0.f);
}

__device__ __forceinline__ float safeden(float x) {
    return (fabsf(x) > 1e-12f) ? x : 1e-12f;
}

// Packed symmetric pair index for i<=j in [0,12): 0..77
__device__ __forceinline__ int pidx(int i, int j) {
    if (i > j) { int t = i; i = j; j = t; }
    return i * 12 - ((i * (i + 1)) >> 1) + j;
}

// Vector reduction: one 16-byte scattered atomic instead of four 4-byte ones.
__device__ __forceinline__ void red_add_v4(float* addr, float a, float b,
                                           float c, float d) {
    asm volatile("red.global.add.v4.f32 [%0], {%1, %2, %3, %4};"
                 :: "l"(addr), "f"(a), "f"(b), "f"(c), "f"(d) : "memory");
}

// ---------------------------------------------------------------------------
// Point-triangle squared distance from 6 Gram entries.
// Classification values are differences/cross-terms of Gram entries computed
// non-contracted -> duplicate-vertex degenerate triangles resolve EXACTLY as
// in the reference where-stack (exact zeros).  Distance is the algebraic
// single-division form with a garbage guard (legit r is in [0, base]).
// Selection order: interior -> BC -> AC -> C -> AB -> B -> A  (A wins).
// ---------------------------------------------------------------------------
__device__ __forceinline__ float tri_dist_g(float g_aa, float g_ab, float g_ac,
                                            float g_bb, float g_bc, float g_cc) {
    float d1 = __fsub_rn(g_aa, g_ab);
    float d2 = __fsub_rn(g_aa, g_ac);
    float d3 = __fsub_rn(g_ab, g_bb);
    float d4 = __fsub_rn(g_ab, g_bc);
    float d5 = __fsub_rn(g_ac, g_bc);
    float d6 = __fsub_rn(g_ac, g_cc);

    float va = __fsub_rn(__fmul_rn(d3, d6), __fmul_rn(d5, d4));
    float vb = __fsub_rn(__fmul_rn(d5, d2), __fmul_rn(d1, d6));
    float vc = __fsub_rn(__fmul_rn(d1, d4), __fmul_rn(d3, d2));
    float e43 = __fsub_rn(d4, d3);
    float e56 = __fsub_rn(d5, d6);

    float base = g_aa;                       // interior (default)
    float num  = vb * d1 + vc * d2;
    float den  = va + vb + vc;
    if ((va <= 0.f) && (e43 >= 0.f) && (e56 >= 0.f)) { base = g_bb; num = e43 * e43; den = e43 + e56; } // BC
    if ((vb <= 0.f) && (d2 >= 0.f) && (d6 <= 0.f))   { base = g_aa; num = d2 * d2;   den = d2 - d6;   } // AC
    if ((d6 >= 0.f) && (d5 <= d6))                   { base = g_cc; num = 0.f; }                        // C
    if ((vc <= 0.f) && (d1 >= 0.f) && (d3 <= 0.f))   { base = g_aa; num = d1 * d1;   den = d1 - d3;   } // AB
    if ((d3 >= 0.f) && (d4 <= d3))                   { base = g_bb; num = 0.f; }                        // B
    if ((d1 <= 0.f) && (d2 <= 0.f))                  { base = g_aa; num = 0.f; }                        // A

    float r = __fdividef(num, safeden(den));
    float d = fmaxf(base - r, 0.f);
    if (!((r >= 0.f) && (base - r >= -1e-4f))) d = base;   // garbage guard
    return d;
}

// ---------------------------------------------------------------------------
// Main kernel: one thread per point; per-point 78-entry Gram matrix in smem.
// ---------------------------------------------------------------------------
__global__ void __launch_bounds__(NT, 5)
pt_dist_kernel(const float* __restrict__ offset,
               const float* __restrict__ points,
               const int*   __restrict__ tri_table,
               float*       __restrict__ out,
               int n_pts)
{
    __shared__ float su[78 * PPB];     // Gram entries, [entry][point]
    __shared__ int   off_s[NSUB * 8];  // per sub-tri: 6 Gram offsets (x PPB), padded to 8

    int tid = threadIdx.x;
    for (int k = tid; k < NSUB; k += NT) {
        int a = tri_table[k * 3 + 0];
        int b = tri_table[k * 3 + 1];
        int c = tri_table[k * 3 + 2];
        off_s[k * 8 + 0] = pidx(a, a) * PPB;
        off_s[k * 8 + 1] = pidx(a, b) * PPB;
        off_s[k * 8 + 2] = pidx(a, c) * PPB;
        off_s[k * 8 + 3] = pidx(b, b) * PPB;
        off_s[k * 8 + 4] = pidx(b, c) * PPB;
        off_s[k * 8 + 5] = pidx(c, c) * PPB;
        off_s[k * 8 + 6] = 0;
        off_s[k * 8 + 7] = 0;
    }

    int i = blockIdx.x * NT + tid;
    bool valid = (i < n_pts);
    int il = valid ? i : (n_pts - 1);

    float px = points[3 * il + 0];
    float py = points[3 * il + 1];
    float pz = points[3 * il + 2];

    int cx = min(max((int)floorf(px), 0), GRIDN - 1);
    int cy = min(max((int)floorf(py), 0), GRIDN - 1);
    int cz = min(max((int)floorf(pz), 0), GRIDN - 1);
    float lx = px - (float)cx;
    float ly = py - (float)cy;
    float lz = pz - (float)cz;

    int cb = cx * NPLANE + cy * 33 + cz;
    const float* o0 = offset;
    const float* o1 = offset + NVOL;
    const float* o2 = offset + 2 * NVOL;

    float t0  = o0[cb];
    float t1  = o1[cb + NPLANE];
    float t2  = o0[cb + 33];
    float t3  = o1[cb];
    float t4  = o0[cb + 1];
    float t5  = o1[cb + NPLANE + 1];
    float t6  = o0[cb + 33 + 1];
    float t7  = o1[cb + 1];
    float t8  = o2[cb];
    float t9  = o2[cb + NPLANE];
    float t10 = o2[cb + NPLANE + 33];
    float t11 = o2[cb + 33];

    // u_e = local - v_e for the 12 edge vertices
    float ux[12], uy[12], uz[12];
    ux[0]  = lx - t0;  uy[0]  = ly;       uz[0]  = lz;
    ux[1]  = lx - 1.f; uy[1]  = ly - t1;  uz[1]  = lz;
    ux[2]  = lx - t2;  uy[2]  = ly - 1.f; uz[2]  = lz;
    ux[3]  = lx;       uy[3]  = ly - t3;  uz[3]  = lz;
    ux[4]  = lx - t4;  uy[4]  = ly;       uz[4]  = lz - 1.f;
    ux[5]  = lx - 1.f; uy[5]  = ly - t5;  uz[5]  = lz - 1.f;
    ux[6]  = lx - t6;  uy[6]  = ly - 1.f; uz[6]  = lz - 1.f;
    ux[7]  = lx;       uy[7]  = ly - t7;  uz[7]  = lz - 1.f;
    ux[8]  = lx;       uy[8]  = ly;       uz[8]  = lz - t8;
    ux[9]  = lx - 1.f; uy[9]  = ly;       uz[9]  = lz - t9;
    ux[10] = lx - 1.f; uy[10] = ly - 1.f; uz[10] = lz - t10;
    ux[11] = lx;       uy[11] = ly - 1.f; uz[11] = lz - t11;

    // 78-entry Gram matrix (contraction OK: equal pairs share one stored value)
    #pragma unroll
    for (int a = 0; a < 12; a++) {
        #pragma unroll
        for (int b = a; b < 12; b++) {
            int p = a * 12 - ((a * (a + 1)) >> 1) + b;   // compile-time after unroll
            su[p * PPB + tid] = ux[a] * ux[b] + uy[a] * uy[b] + uz[a] * uz[b];
        }
    }
    __syncthreads();

    float* outc = out + (size_t)(((cx * GRIDN) + cy) * GRIDN + cz) * T_ROWS;

    #pragma unroll 1
    for (int t = 0; t < T_ROWS; t += 4) {
        float mq[4];
        #pragma unroll
        for (int q = 0; q < 4; q++) {
            float m = 3.402823e38f;
            #pragma unroll
            for (int s = 0; s < 3; s++) {
                int k = (t + q) * 3 + s;
                int4 oA = *(const int4*)&off_s[k * 8];       // (aa, ab, ac, bb)
                int2 oB = *(const int2*)&off_s[k * 8 + 4];   // (bc, cc)
                float g_aa = su[oA.x + tid];
                float g_ab = su[oA.y + tid];
                float g_ac = su[oA.z + tid];
                float g_bb = su[oA.w + tid];
                float g_bc = su[oB.x + tid];
                float g_cc = su[oB.y + tid];
                m = fminf(m, tri_dist_g(g_aa, g_ab, g_ac, g_bb, g_bc, g_cc));
            }
            mq[q] = m;
        }
        if (valid) red_add_v4(outc + t, mq[0], mq[1], mq[2], mq[3]);
    }
}

// ---------------------------------------------------------------------------
extern "C" void kernel_launch(void* const* d_in, const int* in_sizes, int n_in,
                              void* d_out, int out_size) {
    const float* offset    = (const float*)d_in[0];   // (3,33,33,33) fp32
    const float* points    = (const float*)d_in[1];   // (131072,3)   fp32
    const int*   tri_table = (const int*)  d_in[2];   // (48,3,3)     int32
    float* out = (float*)d_out;                       // (32768,48)   fp32

    int n_pts = in_sizes[1] / 3;

    // Request the maximum shared-memory carveout so 5 blocks (5 x ~44.5 KB)
    // can be resident per SM.  Idempotent host-side attribute sets: no
    // allocation, no stream work -- graph-capture safe.
    cudaFuncSetAttribute(pt_dist_kernel,
                         cudaFuncAttributePreferredSharedMemoryCarveout,
                         cudaSharedmemCarveoutMaxShared);

    int n4 = out_size / 4;
    zero_out_kernel<<<(n4 + 255) / 256, 256>>>((float4*)out, n4);

    int blocks = (n_pts + NT - 1) / NT;
    pt_dist_kernel<<<blocks, NT>>>(offset, points, tri_table, out, n_pts);
}